// round 2
// baseline (speedup 1.0000x reference)
#include <cuda_runtime.h>
#include <cstdint>
#include <cstddef>

// Problem constants
#define BB   64
#define TT   256
#define DIN  256
#define HH   1024
#define G4   4096   // 4*H

// ---------------------------------------------------------------------------
// Scratch (allocation-free: __device__ globals)
// ---------------------------------------------------------------------------
__device__ float g_xg[(size_t)BB * TT * G4];   // input-side gate projections, per layer (reused)
__device__ float g_hs_a[(size_t)BB * TT * HH]; // hidden sequence ping
__device__ float g_hs_b[(size_t)BB * TT * HH]; // hidden sequence pong
__device__ float g_h[2][BB * HH];              // recurrent h ping-pong
__device__ float g_c[BB * HH];                 // cell state

// ---------------------------------------------------------------------------
// tf32 helpers
// ---------------------------------------------------------------------------
__device__ __forceinline__ uint32_t f2tf(float f) {
    uint32_t u;
    asm("cvt.rna.tf32.f32 %0, %1;" : "=r"(u) : "f"(f));
    return u;
}

__device__ __forceinline__ void mma8(float c[4], const uint32_t a[4], const uint32_t b[2]) {
    asm volatile(
        "mma.sync.aligned.m16n8k8.row.col.f32.tf32.tf32.f32 "
        "{%0,%1,%2,%3}, {%4,%5,%6,%7}, {%8,%9}, {%0,%1,%2,%3};\n"
        : "+f"(c[0]), "+f"(c[1]), "+f"(c[2]), "+f"(c[3])
        : "r"(a[0]), "r"(a[1]), "r"(a[2]), "r"(a[3]), "r"(b[0]), "r"(b[1]));
}

__device__ __forceinline__ float sigf(float x) { return 1.0f / (1.0f + expf(-x)); }

// ---------------------------------------------------------------------------
// Projection GEMM: g_xg[M,4096] = A[M,K] @ W[4096,K]^T + b1 + b2
// M = B*T = 16384. A selected by a_sel: 0 -> Aext (x), 1 -> g_hs_a, 2 -> g_hs_b
// CTA tile 64x64, BK=16, 128 threads (4 warps, 2x2 of 32x32 warp tiles).
// ---------------------------------------------------------------------------
__global__ void proj_kernel(const float* __restrict__ Aext, int a_sel,
                            const float* __restrict__ W,
                            const float* __restrict__ b1,
                            const float* __restrict__ b2,
                            int K)
{
    __shared__ uint32_t As[16][64 + 4];
    __shared__ uint32_t Bs[16][64 + 4];

    const float* __restrict__ A = (a_sel == 0) ? Aext : (a_sel == 1 ? g_hs_a : g_hs_b);

    const int tid  = threadIdx.x;
    const int m0   = blockIdx.y * 64;
    const int n0   = blockIdx.x * 64;
    const int warp = tid >> 5, lane = tid & 31;
    const int gid  = lane >> 2, tq = lane & 3;
    const int wmo  = (warp >> 1) * 32;
    const int wno  = (warp & 1) * 32;

    float acc[2][4][4];
#pragma unroll
    for (int i = 0; i < 2; i++)
#pragma unroll
        for (int j = 0; j < 4; j++)
#pragma unroll
            for (int q = 0; q < 4; q++) acc[i][j][q] = 0.0f;

    for (int k0 = 0; k0 < K; k0 += 16) {
#pragma unroll
        for (int r = 0; r < 2; r++) {
            int lin = tid + r * 128;           // 0..255
            int row = lin >> 2;
            int cv  = (lin & 3) * 4;
            float4 va = *reinterpret_cast<const float4*>(&A[(size_t)(m0 + row) * K + k0 + cv]);
            As[cv + 0][row] = f2tf(va.x);
            As[cv + 1][row] = f2tf(va.y);
            As[cv + 2][row] = f2tf(va.z);
            As[cv + 3][row] = f2tf(va.w);
            float4 vw = *reinterpret_cast<const float4*>(&W[(size_t)(n0 + row) * K + k0 + cv]);
            Bs[cv + 0][row] = f2tf(vw.x);
            Bs[cv + 1][row] = f2tf(vw.y);
            Bs[cv + 2][row] = f2tf(vw.z);
            Bs[cv + 3][row] = f2tf(vw.w);
        }
        __syncthreads();

#pragma unroll
        for (int kk = 0; kk < 2; kk++) {
            uint32_t af[2][4];
#pragma unroll
            for (int i = 0; i < 2; i++) {
                int r0 = wmo + i * 16 + gid;
                af[i][0] = As[kk * 8 + tq][r0];
                af[i][1] = As[kk * 8 + tq][r0 + 8];
                af[i][2] = As[kk * 8 + tq + 4][r0];
                af[i][3] = As[kk * 8 + tq + 4][r0 + 8];
            }
#pragma unroll
            for (int j = 0; j < 4; j++) {
                uint32_t bf[2];
                int n = wno + j * 8 + gid;
                bf[0] = Bs[kk * 8 + tq][n];
                bf[1] = Bs[kk * 8 + tq + 4][n];
#pragma unroll
                for (int i = 0; i < 2; i++) mma8(acc[i][j], af[i], bf);
            }
        }
        __syncthreads();
    }

    // epilogue: add biases, store to g_xg
#pragma unroll
    for (int j = 0; j < 4; j++) {
        int col = n0 + wno + j * 8 + 2 * tq;
        float bb0 = b1[col] + b2[col];
        float bb1 = b1[col + 1] + b2[col + 1];
#pragma unroll
        for (int i = 0; i < 2; i++) {
            int row = m0 + wmo + i * 16 + gid;
            g_xg[(size_t)row * G4 + col]       = acc[i][j][0] + bb0;
            g_xg[(size_t)row * G4 + col + 1]   = acc[i][j][1] + bb1;
            g_xg[(size_t)(row + 8) * G4 + col]     = acc[i][j][2] + bb0;
            g_xg[(size_t)(row + 8) * G4 + col + 1] = acc[i][j][3] + bb1;
        }
    }
}

// ---------------------------------------------------------------------------
// Zero h/c at layer start
// ---------------------------------------------------------------------------
__global__ void zero_kernel()
{
    int i = blockIdx.x * blockDim.x + threadIdx.x;
    if (i < BB * HH) {
        g_h[0][i] = 0.0f;
        g_h[1][i] = 0.0f;
        g_c[i]    = 0.0f;
    }
}

// ---------------------------------------------------------------------------
// Fused recurrent step: one CTA owns 8 hidden units (= 32 gate columns
// i/f/g/o). Computes gates = h_prev @ Whh_sel^T, exchanges via SMEM, applies
// LSTM pointwise update, writes h_out + hidden sequence.
// Grid: 128 CTAs x 128 threads. h ping-pongs on t parity.
// hs_sel: 1 -> g_hs_a, 2 -> g_hs_b
// ---------------------------------------------------------------------------
__global__ void step_kernel(const float* __restrict__ Whh, int t, int hs_sel)
{
    __shared__ uint32_t As[16][64 + 4];
    __shared__ uint32_t Bs[16][32 + 4];
    __shared__ float    Gsm[64][33];

    const float* __restrict__ h_in  = g_h[t & 1];
    float* __restrict__       h_out = g_h[(t + 1) & 1];
    float* __restrict__       hs    = (hs_sel == 1) ? g_hs_a : g_hs_b;

    const int tid  = threadIdx.x;
    const int j0   = blockIdx.x * 8;    // first hidden unit of this CTA
    const int warp = tid >> 5, lane = tid & 31;
    const int gid  = lane >> 2, tq = lane & 3;
    const int wmo  = (warp >> 1) * 32;  // warp row offset (0 / 32)
    const int wno  = (warp & 1) * 16;   // warp col offset (0 / 16)

    float acc[2][2][4];
#pragma unroll
    for (int i = 0; i < 2; i++)
#pragma unroll
        for (int j = 0; j < 2; j++)
#pragma unroll
            for (int q = 0; q < 4; q++) acc[i][j][q] = 0.0f;

    for (int k0 = 0; k0 < HH; k0 += 16) {
        // load A (h_prev): 64 rows x 16 k -> 2 float4 per thread
#pragma unroll
        for (int r = 0; r < 2; r++) {
            int lin = tid + r * 128;
            int row = lin >> 2;
            int cv  = (lin & 3) * 4;
            float4 va = *reinterpret_cast<const float4*>(&h_in[row * HH + k0 + cv]);
            As[cv + 0][row] = f2tf(va.x);
            As[cv + 1][row] = f2tf(va.y);
            As[cv + 2][row] = f2tf(va.z);
            As[cv + 3][row] = f2tf(va.w);
        }
        // load B (Whh rows for 4 gates x 8 units): 32 cols x 16 k -> 1 float4/thread
        {
            int colc = tid >> 2;            // 0..31 : col = gate*8 + jj
            int cv   = (tid & 3) * 4;
            int wrow = (colc >> 3) * HH + j0 + (colc & 7);
            float4 vw = *reinterpret_cast<const float4*>(&Whh[(size_t)wrow * HH + k0 + cv]);
            Bs[cv + 0][colc] = f2tf(vw.x);
            Bs[cv + 1][colc] = f2tf(vw.y);
            Bs[cv + 2][colc] = f2tf(vw.z);
            Bs[cv + 3][colc] = f2tf(vw.w);
        }
        __syncthreads();

#pragma unroll
        for (int kk = 0; kk < 2; kk++) {
            uint32_t af[2][4];
#pragma unroll
            for (int i = 0; i < 2; i++) {
                int r0 = wmo + i * 16 + gid;
                af[i][0] = As[kk * 8 + tq][r0];
                af[i][1] = As[kk * 8 + tq][r0 + 8];
                af[i][2] = As[kk * 8 + tq + 4][r0];
                af[i][3] = As[kk * 8 + tq + 4][r0 + 8];
            }
#pragma unroll
            for (int j = 0; j < 2; j++) {
                uint32_t bf[2];
                int n = wno + j * 8 + gid;
                bf[0] = Bs[kk * 8 + tq][n];
                bf[1] = Bs[kk * 8 + tq + 4][n];
#pragma unroll
                for (int i = 0; i < 2; i++) mma8(acc[i][j], af[i], bf);
            }
        }
        __syncthreads();
    }

    // scatter gate partials to SMEM for the pointwise exchange
#pragma unroll
    for (int j = 0; j < 2; j++) {
        int colc = wno + j * 8 + 2 * tq;
#pragma unroll
        for (int i = 0; i < 2; i++) {
            int row = wmo + i * 16 + gid;
            Gsm[row][colc]         = acc[i][j][0];
            Gsm[row][colc + 1]     = acc[i][j][1];
            Gsm[row + 8][colc]     = acc[i][j][2];
            Gsm[row + 8][colc + 1] = acc[i][j][3];
        }
    }
    __syncthreads();

    // pointwise LSTM update: 64 batches x 8 units = 512 over 128 threads
#pragma unroll
    for (int s = 0; s < 4; s++) {
        int p  = tid + s * 128;
        int b  = p >> 3;
        int jj = p & 7;
        int j  = j0 + jj;
        const float* __restrict__ xgp = &g_xg[((size_t)(b * TT + t)) * G4 + j];
        float iv = Gsm[b][jj]      + xgp[0];
        float fv = Gsm[b][8 + jj]  + xgp[HH];
        float gv = Gsm[b][16 + jj] + xgp[2 * HH];
        float ov = Gsm[b][24 + jj] + xgp[3 * HH];

        float co = g_c[b * HH + j];
        float cn = sigf(fv) * co + sigf(iv) * tanhf(gv);
        float hn = sigf(ov) * tanhf(cn);

        g_c[b * HH + j]  = cn;
        h_out[b * HH + j] = hn;
        hs[((size_t)(b * TT + t)) * HH + j] = hn;
    }
}

// ---------------------------------------------------------------------------
// Final FC: out[b] = dot(hs_a[b, T-1, :], fc_w) + fc_b[0]
// ---------------------------------------------------------------------------
__global__ void fc_kernel(const float* __restrict__ fw,
                          const float* __restrict__ fb,
                          float* __restrict__ out)
{
    __shared__ float red[8];
    int b   = blockIdx.x;
    int tid = threadIdx.x;
    const float* __restrict__ hr = &g_hs_a[((size_t)(b * TT + (TT - 1))) * HH];

    float s = 0.0f;
    for (int j = tid; j < HH; j += blockDim.x) s += hr[j] * fw[j];

#pragma unroll
    for (int o = 16; o > 0; o >>= 1) s += __shfl_down_sync(0xffffffffu, s, o);
    if ((tid & 31) == 0) red[tid >> 5] = s;
    __syncthreads();
    if (tid == 0) {
        float tot = 0.0f;
        int nw = blockDim.x / 32;
        for (int w = 0; w < nw; w++) tot += red[w];
        out[b] = tot + fb[0];
    }
}

// ---------------------------------------------------------------------------
// Launch: 3 x (proj + zero + 256 steps) + fc  (all graph-capturable)
// ---------------------------------------------------------------------------
extern "C" void kernel_launch(void* const* d_in, const int* in_sizes, int n_in,
                              void* d_out, int out_size)
{
    const float* x     = (const float*)d_in[0];
    const float* w_ih[3] = { (const float*)d_in[1], (const float*)d_in[5], (const float*)d_in[9] };
    const float* w_hh[3] = { (const float*)d_in[2], (const float*)d_in[6], (const float*)d_in[10] };
    const float* b_ih[3] = { (const float*)d_in[3], (const float*)d_in[7], (const float*)d_in[11] };
    const float* b_hh[3] = { (const float*)d_in[4], (const float*)d_in[8], (const float*)d_in[12] };
    const float* fc_w  = (const float*)d_in[13];
    const float* fc_b  = (const float*)d_in[14];
    float* out = (float*)d_out;

    dim3 pgrid(G4 / 64, (BB * TT) / 64);
    dim3 sgrid(HH / 8);
    int  zgrid = (BB * HH + 255) / 256;

    // a_sel: input for each layer's projection; hs_sel: where steps write hs
    // layer0: A=x (0), hs -> a (1)
    // layer1: A=hs_a (1), hs -> b (2)
    // layer2: A=hs_b (2), hs -> a (1)
    const int a_sel[3]  = { 0, 1, 2 };
    const int hs_sel[3] = { 1, 2, 1 };
    const int K_in[3]   = { DIN, HH, HH };

    for (int l = 0; l < 3; l++) {
        proj_kernel<<<pgrid, 128>>>(x, a_sel[l], w_ih[l], b_ih[l], b_hh[l], K_in[l]);
        zero_kernel<<<zgrid, 256>>>();
        for (int t = 0; t < TT; t++) {
            step_kernel<<<sgrid, 128>>>(w_hh[l], t, hs_sel[l]);
        }
    }
    fc_kernel<<<BB, 256>>>(fc_w, fc_b, out);
}

// round 5
// speedup vs baseline: 2.5410x; 2.5410x over previous
#include <cuda_runtime.h>
#include <cuda_bf16.h>
#include <cstdint>
#include <cstddef>

// Problem constants
#define BB   64
#define TT   256
#define DIN  256
#define HH   1024
#define G4   4096
#define NCTA 128

// Persistent-kernel SMEM layout (bf16 elems)
#define WS   1032          // weight row stride (1024 + 8 pad)
#define KC   128           // K chunk
#define AS   136           // A row stride (128 + 8 pad)
#define PERSIST_SMEM (124*1024)

// ---------------------------------------------------------------------------
// Scratch (allocation-free: __device__ globals)
// ---------------------------------------------------------------------------
__device__ float          g_xg[(size_t)BB * TT * G4];
__device__ __nv_bfloat16  g_hs_a[(size_t)BB * TT * HH];
__device__ __nv_bfloat16  g_hs_b[(size_t)BB * TT * HH];
__device__ __nv_bfloat16  g_hbuf[2][BB * HH];
__device__ unsigned       g_flags[NCTA];

// ---------------------------------------------------------------------------
// helpers
// ---------------------------------------------------------------------------
__device__ __forceinline__ uint32_t packbf(float lo, float hi) {
    uint32_t r;
    asm("cvt.rn.bf16x2.f32 %0, %1, %2;" : "=r"(r) : "f"(hi), "f"(lo));
    return r;
}

__device__ __forceinline__ void mma_bf16(float c[4], uint32_t a0, uint32_t a1,
                                         uint32_t a2, uint32_t a3,
                                         uint32_t b0, uint32_t b1) {
    asm volatile(
        "mma.sync.aligned.m16n8k16.row.col.f32.bf16.bf16.f32 "
        "{%0,%1,%2,%3}, {%4,%5,%6,%7}, {%8,%9}, {%0,%1,%2,%3};\n"
        : "+f"(c[0]), "+f"(c[1]), "+f"(c[2]), "+f"(c[3])
        : "r"(a0), "r"(a1), "r"(a2), "r"(a3), "r"(b0), "r"(b1));
}

__device__ __forceinline__ unsigned ld_acq(const unsigned* p) {
    unsigned v;
    asm volatile("ld.acquire.gpu.u32 %0, [%1];" : "=r"(v) : "l"(p));
    return v;
}
__device__ __forceinline__ void st_rel(unsigned* p, unsigned v) {
    asm volatile("st.release.gpu.u32 [%0], %1;" :: "l"(p), "r"(v));
}

__device__ __forceinline__ float sigf(float x) { return 1.0f / (1.0f + __expf(-x)); }

// ---------------------------------------------------------------------------
// Persistent recurrent kernel: one layer, all 256 steps.
// 128 CTAs x 256 threads, 1 CTA/SM (forced via 124KB dynamic smem).
// CTA c owns hidden units j0 = 8c .. 8c+7 (32 gate columns i/f/g/o).
// Weights (32 rows x 1024, bf16) stationary in SMEM.
// Cross-CTA per-step sync via release/acquire flags; h ping-pongs in global bf16.
// ---------------------------------------------------------------------------
__global__ void __launch_bounds__(256, 1)
persist_kernel(const float* __restrict__ Whh, int hs_sel)
{
    extern __shared__ __align__(16) unsigned char smem[];
    __nv_bfloat16* Wsm = (__nv_bfloat16*)smem;                         // [32][WS]
    __nv_bfloat16* Asm = (__nv_bfloat16*)(smem + 32 * WS * 2);         // [2][64][AS]
    float*         Gsm = (float*)(smem + 32 * WS * 2 + 2 * 64 * AS * 2); // [64][33]

    const int tid  = threadIdx.x;
    const int cta  = blockIdx.x;
    const int j0   = cta * 8;
    const int warp = tid >> 5, lane = tid & 31;
    const int g    = lane >> 2, tq = lane & 3;
    const int wm16 = (warp >> 1) * 16;   // warp row offset (0/16/32/48)
    const int wn16 = (warp & 1) * 16;    // warp col offset (0/16)
    const int rot  = cta & 7;

    // ---- gather + convert weights (once per layer) ----
    for (int idx = tid; idx < 32 * (HH / 4); idx += 256) {
        int c    = idx >> 8;            // local col 0..31
        int k4   = (idx & 255) * 4;
        int gate = c >> 3, j = j0 + (c & 7);
        float4 w = *(const float4*)(Whh + (size_t)(gate * HH + j) * HH + k4);
        uint32_t* dst = (uint32_t*)(Wsm + c * WS + k4);
        dst[0] = packbf(w.x, w.y);
        dst[1] = packbf(w.z, w.w);
    }
    __syncthreads();

    const uint32_t* W32 = (const uint32_t*)Wsm;

    float cst[2] = {0.0f, 0.0f};   // cell state (2 elems per thread)

    for (int t = 0; t < TT; t++) {
        const __nv_bfloat16* __restrict__ hin = g_hbuf[t & 1];

        // prefetch xg for this step's pointwise
        float xv[2][4];
#pragma unroll
        for (int s = 0; s < 2; s++) {
            int p = tid + s * 256, b = p >> 3, jj = p & 7;
            const float* xp = g_xg + ((size_t)(b * TT + t)) * G4 + j0 + jj;
            xv[s][0] = xp[0];
            xv[s][1] = xp[HH];
            xv[s][2] = xp[2 * HH];
            xv[s][3] = xp[3 * HH];
        }

        float acc[2][4];
#pragma unroll
        for (int ns = 0; ns < 2; ns++)
#pragma unroll
            for (int q = 0; q < 4; q++) acc[ns][q] = 0.0f;

        // ---- chunk loader (flag-gated) ----
        auto load_chunk = [&](int kc, int buf) {
            int sub  = tid & 15;
            int fidx = kc * 16 + sub;
            if (fidx != cta) {
                while ((int)ld_acq(&g_flags[fidx]) < t) {}
            }
#pragma unroll
            for (int r = 0; r < 4; r++) {
                int lin = tid + r * 256;
                int row = lin >> 4;
                int c8  = (lin & 15) * 8;
                uint4 v = *(const uint4*)(hin + row * HH + kc * KC + c8);
                *(uint4*)(Asm + buf * 64 * AS + row * AS + c8) = v;
            }
        };

        auto compute_chunk = [&](int kc, int buf) {
            const uint32_t* A32 = (const uint32_t*)Asm + buf * (64 * AS / 2);
            const int kcw = kc * (KC / 2);
#pragma unroll
            for (int q = 0; q < 8; q++) {
                int q8 = q * 8;
                int r0 = wm16 + g;
                uint32_t a0 = A32[r0 * (AS / 2) + q8 + tq];
                uint32_t a1 = A32[(r0 + 8) * (AS / 2) + q8 + tq];
                uint32_t a2 = A32[r0 * (AS / 2) + q8 + tq + 4];
                uint32_t a3 = A32[(r0 + 8) * (AS / 2) + q8 + tq + 4];
#pragma unroll
                for (int ns = 0; ns < 2; ns++) {
                    const uint32_t* wp = W32 + (wn16 + ns * 8 + g) * (WS / 2) + kcw + q8 + tq;
                    mma_bf16(acc[ns], a0, a1, a2, a3, wp[0], wp[4]);
                }
            }
        };

        // ---- pipelined K loop: 8 chunks of 128 ----
        load_chunk(rot, 0);
        __syncthreads();
#pragma unroll 1
        for (int i = 0; i < 8; i++) {
            if (i + 1 < 8) load_chunk((i + 1 + rot) & 7, (i + 1) & 1);
            compute_chunk((i + rot) & 7, i & 1);
            __syncthreads();
        }

        // ---- gate exchange through SMEM ----
#pragma unroll
        for (int ns = 0; ns < 2; ns++) {
            int col = wn16 + ns * 8 + 2 * tq;
            int row = wm16 + g;
            Gsm[row * 33 + col]           = acc[ns][0];
            Gsm[row * 33 + col + 1]       = acc[ns][1];
            Gsm[(row + 8) * 33 + col]     = acc[ns][2];
            Gsm[(row + 8) * 33 + col + 1] = acc[ns][3];
        }
        __syncthreads();

        // ---- pointwise LSTM update ----
        __nv_bfloat16* __restrict__ hout = g_hbuf[(t + 1) & 1];
#pragma unroll
        for (int s = 0; s < 2; s++) {
            int p = tid + s * 256, b = p >> 3, jj = p & 7;
            int j = j0 + jj;
            float iv = Gsm[b * 33 + jj]      + xv[s][0];
            float fv = Gsm[b * 33 + 8 + jj]  + xv[s][1];
            float gv = Gsm[b * 33 + 16 + jj] + xv[s][2];
            float ov = Gsm[b * 33 + 24 + jj] + xv[s][3];

            float cn = sigf(fv) * cst[s] + sigf(iv) * tanhf(gv);
            float hn = sigf(ov) * tanhf(cn);
            cst[s] = cn;

            __nv_bfloat16 hb = __float2bfloat16(hn);
            hout[b * HH + j] = hb;
            if (hs_sel == 1)      g_hs_a[((size_t)(b * TT + t)) * HH + j] = hb;
            else if (hs_sel == 2) g_hs_b[((size_t)(b * TT + t)) * HH + j] = hb;
        }
        __syncthreads();
        if (tid == 0) {
            __threadfence();
            st_rel(&g_flags[cta], (unsigned)(t + 1));
        }
    }
}

// ---------------------------------------------------------------------------
// Reset h state + flags before each layer's persistent kernel
// ---------------------------------------------------------------------------
__global__ void reset_kernel()
{
    int i = blockIdx.x * blockDim.x + threadIdx.x;
    if (i < BB * HH) {
        g_hbuf[0][i] = __float2bfloat16(0.0f);
        g_hbuf[1][i] = __float2bfloat16(0.0f);
    }
    if (i < NCTA) g_flags[i] = 0;
}

// ---------------------------------------------------------------------------
// Projection GEMM (bf16 mma): g_xg[M,4096] = A[M,K] @ W[4096,K]^T + b1 + b2
// CTA tile 128x64, Kchunk 32, 256 threads (8 warps, 4x2 of 32x32 warp tiles).
// a_sel: 0 -> x (fp32, K=256), 1 -> g_hs_a (bf16), 2 -> g_hs_b (bf16)
// ---------------------------------------------------------------------------
__global__ void __launch_bounds__(256)
proj_kernel(const float* __restrict__ Axf, int a_sel,
            const float* __restrict__ W,
            const float* __restrict__ b1,
            const float* __restrict__ b2,
            int K)
{
    __shared__ __align__(16) __nv_bfloat16 Asb[2][128 * 40];
    __shared__ __align__(16) __nv_bfloat16 Bsb[2][64 * 40];
    __shared__ float bsm[64];

    const int tid  = threadIdx.x;
    const int m0   = blockIdx.y * 128;
    const int n0   = blockIdx.x * 64;
    const int warp = tid >> 5, lane = tid & 31;
    const int g    = lane >> 2, tq = lane & 3;
    const int wm32 = (warp >> 1) * 32;
    const int wn32 = (warp & 1) * 32;

    if (tid < 64) bsm[tid] = b1[n0 + tid] + b2[n0 + tid];

    float acc[2][4][4];
#pragma unroll
    for (int i = 0; i < 2; i++)
#pragma unroll
        for (int j = 0; j < 4; j++)
#pragma unroll
            for (int q = 0; q < 4; q++) acc[i][j][q] = 0.0f;

    const __nv_bfloat16* Abf = (a_sel == 1) ? g_hs_a : g_hs_b;

    auto load_chunk = [&](int kc, int buf) {
        // A: 128 rows x 32 k
        {
            int row  = tid >> 1;
            int half = (tid & 1) * 16;
            uint32_t pk[8];
            if (a_sel == 0) {
                const float* src = Axf + (size_t)(m0 + row) * K + kc * 32 + half;
                const float4 v0 = *(const float4*)(src);
                const float4 v1 = *(const float4*)(src + 4);
                const float4 v2 = *(const float4*)(src + 8);
                const float4 v3 = *(const float4*)(src + 12);
                pk[0] = packbf(v0.x, v0.y); pk[1] = packbf(v0.z, v0.w);
                pk[2] = packbf(v1.x, v1.y); pk[3] = packbf(v1.z, v1.w);
                pk[4] = packbf(v2.x, v2.y); pk[5] = packbf(v2.z, v2.w);
                pk[6] = packbf(v3.x, v3.y); pk[7] = packbf(v3.z, v3.w);
            } else {
                const uint4* src = (const uint4*)(Abf + (size_t)(m0 + row) * K + kc * 32 + half);
                uint4 u0 = src[0], u1 = src[1];
                pk[0] = u0.x; pk[1] = u0.y; pk[2] = u0.z; pk[3] = u0.w;
                pk[4] = u1.x; pk[5] = u1.y; pk[6] = u1.z; pk[7] = u1.w;
            }
            uint4* dst = (uint4*)(Asb[buf] + row * 40 + half);
            dst[0] = make_uint4(pk[0], pk[1], pk[2], pk[3]);
            dst[1] = make_uint4(pk[4], pk[5], pk[6], pk[7]);
        }
        // B: 64 rows x 32 k
        {
            int n  = tid >> 2;
            int q8 = (tid & 3) * 8;
            const float* src = W + (size_t)(n0 + n) * K + kc * 32 + q8;
            const float4 v0 = *(const float4*)(src);
            const float4 v1 = *(const float4*)(src + 4);
            uint4 pk = make_uint4(packbf(v0.x, v0.y), packbf(v0.z, v0.w),
                                  packbf(v1.x, v1.y), packbf(v1.z, v1.w));
            *(uint4*)(Bsb[buf] + n * 40 + q8) = pk;
        }
    };

    auto compute_chunk = [&](int buf) {
        const uint32_t* A32 = (const uint32_t*)Asb[buf];
        const uint32_t* B32 = (const uint32_t*)Bsb[buf];
#pragma unroll
        for (int q = 0; q < 2; q++) {
            int q8 = q * 8;
            uint32_t a[2][4];
#pragma unroll
            for (int i = 0; i < 2; i++) {
                int r = wm32 + i * 16 + g;
                a[i][0] = A32[r * 20 + q8 + tq];
                a[i][1] = A32[(r + 8) * 20 + q8 + tq];
                a[i][2] = A32[r * 20 + q8 + tq + 4];
                a[i][3] = A32[(r + 8) * 20 + q8 + tq + 4];
            }
#pragma unroll
            for (int j = 0; j < 4; j++) {
                const uint32_t* bp = B32 + (wn32 + j * 8 + g) * 20 + q8 + tq;
                uint32_t b0 = bp[0], b1v = bp[4];
#pragma unroll
                for (int i = 0; i < 2; i++)
                    mma_bf16(acc[i][j], a[i][0], a[i][1], a[i][2], a[i][3], b0, b1v);
            }
        }
    };

    const int nk = K / 32;
    load_chunk(0, 0);
    __syncthreads();
#pragma unroll 1
    for (int i = 0; i < nk; i++) {
        if (i + 1 < nk) load_chunk(i + 1, (i + 1) & 1);
        compute_chunk(i & 1);
        __syncthreads();
    }

    // epilogue
#pragma unroll
    for (int i = 0; i < 2; i++)
#pragma unroll
        for (int j = 0; j < 4; j++) {
            int row  = m0 + wm32 + i * 16 + g;
            int lcol = wn32 + j * 8 + 2 * tq;
            int col  = n0 + lcol;
            float bb0 = bsm[lcol], bb1 = bsm[lcol + 1];
            g_xg[(size_t)row * G4 + col]           = acc[i][j][0] + bb0;
            g_xg[(size_t)row * G4 + col + 1]       = acc[i][j][1] + bb1;
            g_xg[(size_t)(row + 8) * G4 + col]     = acc[i][j][2] + bb0;
            g_xg[(size_t)(row + 8) * G4 + col + 1] = acc[i][j][3] + bb1;
        }
}

// ---------------------------------------------------------------------------
// Final FC: out[b] = dot(h_final[b, :], fc_w) + fc_b[0]
// h_final = g_hbuf[0] (after 256 steps, (255+1)&1 == 0)
// ---------------------------------------------------------------------------
__global__ void fc_kernel(const float* __restrict__ fw,
                          const float* __restrict__ fb,
                          float* __restrict__ out)
{
    __shared__ float red[8];
    int b   = blockIdx.x;
    int tid = threadIdx.x;
    const __nv_bfloat16* __restrict__ hr = g_hbuf[0] + b * HH;

    float s = 0.0f;
    for (int j = tid; j < HH; j += blockDim.x)
        s += __bfloat162float(hr[j]) * fw[j];

#pragma unroll
    for (int o = 16; o > 0; o >>= 1) s += __shfl_down_sync(0xffffffffu, s, o);
    if ((tid & 31) == 0) red[tid >> 5] = s;
    __syncthreads();
    if (tid == 0) {
        float tot = 0.0f;
        int nw = blockDim.x / 32;
        for (int w = 0; w < nw; w++) tot += red[w];
        out[b] = tot + fb[0];
    }
}

// ---------------------------------------------------------------------------
// Launch: 3 x (proj + reset + persist) + fc  (7+3 nodes, graph-capturable)
// ---------------------------------------------------------------------------
extern "C" void kernel_launch(void* const* d_in, const int* in_sizes, int n_in,
                              void* d_out, int out_size)
{
    const float* x       = (const float*)d_in[0];
    const float* w_ih[3] = { (const float*)d_in[1], (const float*)d_in[5], (const float*)d_in[9]  };
    const float* w_hh[3] = { (const float*)d_in[2], (const float*)d_in[6], (const float*)d_in[10] };
    const float* b_ih[3] = { (const float*)d_in[3], (const float*)d_in[7], (const float*)d_in[11] };
    const float* b_hh[3] = { (const float*)d_in[4], (const float*)d_in[8], (const float*)d_in[12] };
    const float* fc_w    = (const float*)d_in[13];
    const float* fc_b    = (const float*)d_in[14];
    float* out = (float*)d_out;

    cudaFuncSetAttribute(persist_kernel,
                         cudaFuncAttributeMaxDynamicSharedMemorySize, PERSIST_SMEM);

    const int a_sel[3]  = { 0, 1, 2 };
    const int hs_sel[3] = { 1, 2, 0 };   // layer2 hidden sequence not needed
    const int K_in[3]   = { DIN, HH, HH };

    dim3 pgrid(G4 / 64, (BB * TT) / 128);

    for (int l = 0; l < 3; l++) {
        proj_kernel<<<pgrid, 256>>>(x, a_sel[l], w_ih[l], b_ih[l], b_hh[l], K_in[l]);
        reset_kernel<<<(BB * HH + 255) / 256, 256>>>();
        persist_kernel<<<NCTA, 256, PERSIST_SMEM>>>(w_hh[l], hs_sel[l]);
    }
    fc_kernel<<<BB, 256>>>(fc_w, fc_b, out);
}

// round 7
// speedup vs baseline: 3.3502x; 1.3185x over previous
#include <cuda_runtime.h>
#include <cuda_bf16.h>
#include <cstdint>
#include <cstddef>

// Problem constants
#define BB   64
#define TT   256
#define DIN  256
#define HH   1024
#define G4   4096
#define NCTA 128

// persist smem layout (bf16 elems)
#define WS2  1032            // weight row stride (1024 + 8)
#define AS2  264             // h chunk row stride (256 + 8)
#define KC   256             // K chunk
#define PERSIST_SMEM 208000  // 64*1032*2 + 4*32*264*2 + 32*65*4

// proj smem layout
#define PS    40             // row stride elems (32 + 8)
#define PTILE (128*PS)       // elems per stage per operand
#define PROJ_SMEM (3*PTILE*2*2 + 512)

// ---------------------------------------------------------------------------
// Scratch (allocation-free: __device__ globals)
// ---------------------------------------------------------------------------
__device__ __align__(128) float          g_xg[(size_t)BB * TT * G4];
__device__ __align__(128) __nv_bfloat16  g_hs_a[(size_t)BB * TT * HH];
__device__ __align__(128) __nv_bfloat16  g_hs_b[(size_t)BB * TT * HH];
__device__ __align__(128) __nv_bfloat16  g_hbuf[2][BB * HH];
__device__ __align__(128) __nv_bfloat16  g_xb[(size_t)BB * TT * DIN];
__device__ __align__(128) __nv_bfloat16  g_wb[(size_t)(G4 * DIN + 2 * G4 * HH)];
__device__ unsigned g_flags[NCTA];

// ---------------------------------------------------------------------------
// helpers
// ---------------------------------------------------------------------------
__device__ __forceinline__ uint32_t packbf(float lo, float hi) {
    uint32_t r;
    asm("cvt.rn.bf16x2.f32 %0, %1, %2;" : "=r"(r) : "f"(hi), "f"(lo));
    return r;
}

__device__ __forceinline__ void mma_bf16(float c[4], const uint32_t a[4],
                                         uint32_t b0, uint32_t b1) {
    asm volatile(
        "mma.sync.aligned.m16n8k16.row.col.f32.bf16.bf16.f32 "
        "{%0,%1,%2,%3}, {%4,%5,%6,%7}, {%8,%9}, {%0,%1,%2,%3};\n"
        : "+f"(c[0]), "+f"(c[1]), "+f"(c[2]), "+f"(c[3])
        : "r"(a[0]), "r"(a[1]), "r"(a[2]), "r"(a[3]), "r"(b0), "r"(b1));
}

__device__ __forceinline__ uint32_t smem_u32(const void* p) {
    return (uint32_t)__cvta_generic_to_shared(p);
}

__device__ __forceinline__ void ldsm4(uint32_t r[4], uint32_t addr) {
    asm volatile("ldmatrix.sync.aligned.m8n8.x4.shared.b16 {%0,%1,%2,%3}, [%4];\n"
                 : "=r"(r[0]), "=r"(r[1]), "=r"(r[2]), "=r"(r[3]) : "r"(addr));
}

__device__ __forceinline__ void cp16(uint32_t daddr, const void* src) {
    asm volatile("cp.async.cg.shared.global [%0], [%1], 16;\n"
                 :: "r"(daddr), "l"(src));
}
#define CP_COMMIT() asm volatile("cp.async.commit_group;\n")
template <int N> __device__ __forceinline__ void cp_wait() {
    asm volatile("cp.async.wait_group %0;\n" :: "n"(N));
}

__device__ __forceinline__ unsigned ld_acq(const unsigned* p) {
    unsigned v;
    asm volatile("ld.acquire.gpu.u32 %0, [%1];" : "=r"(v) : "l"(p));
    return v;
}
__device__ __forceinline__ void st_rel(unsigned* p, unsigned v) {
    asm volatile("st.release.gpu.u32 [%0], %1;" :: "l"(p), "r"(v));
}

__device__ __forceinline__ float sigf(float x) { return 1.0f / (1.0f + __expf(-x)); }

// ---------------------------------------------------------------------------
// fp32 -> bf16 convert (x and w_ih weights, once per launch)
// ---------------------------------------------------------------------------
__global__ void conv_kernel(const float* __restrict__ src, int dsel,
                            size_t off, int n4)
{
    int i = blockIdx.x * blockDim.x + threadIdx.x;
    if (i >= n4) return;
    float4 v = ((const float4*)src)[i];
    __nv_bfloat16* dst = (dsel == 0 ? g_xb : g_wb) + off;
    uint32_t* d = (uint32_t*)dst + (size_t)i * 2;
    d[0] = packbf(v.x, v.y);
    d[1] = packbf(v.z, v.w);
}

// ---------------------------------------------------------------------------
// Persistent recurrent kernel: 128 CTAs = 2 batch-halves x 64 unit-groups.
// CTA (bh, ug): batches bh*32..+31, hidden units ug*16..+15 (64 gate cols).
// Weights [64][1024] bf16 stationary in SMEM. h chunks via cp.async.
// ldmatrix + mma.m16n8k16. Whole-step flag sync (64 flags per batch half).
// ---------------------------------------------------------------------------
__global__ void __launch_bounds__(256, 1)
persist_kernel(const float* __restrict__ Whh, int hs_sel)
{
    extern __shared__ __align__(16) unsigned char smem[];
    __nv_bfloat16* Wsm = (__nv_bfloat16*)smem;            // [64][WS2]
    __nv_bfloat16* Asm = Wsm + 64 * WS2;                  // [4][32][AS2]
    float*         Gsm = (float*)(Asm + 4 * 32 * AS2);    // [32][65]

    const int tid  = threadIdx.x;
    const int cta  = blockIdx.x;
    const int bh   = cta >> 6;
    const int ug   = cta & 63;
    const int j0   = ug * 16;
    const int b0   = bh * 32;
    const int warp = tid >> 5, lane = tid & 31;
    const int g    = lane >> 2, tq = lane & 3;
    const int wm   = (warp >> 2) * 16;    // 0 / 16
    const int wn   = (warp & 3) * 16;     // 0 / 16 / 32 / 48
    const int lrow = lane & 15;
    const int lhi  = (lane >> 4) * 8;

    // ---- gather + convert weights (once per layer) ----
    for (int idx = tid; idx < 64 * 256; idx += 256) {
        int n = idx >> 8;  int k4 = (idx & 255) * 4;
        int gate = n >> 4, u = n & 15;
        float4 w = *(const float4*)(Whh + (size_t)(gate * HH + j0 + u) * HH + k4);
        uint32_t* dst = (uint32_t*)(Wsm + n * WS2 + k4);
        dst[0] = packbf(w.x, w.y);
        dst[1] = packbf(w.z, w.w);
    }
    __syncthreads();

    float cst[2] = {0.0f, 0.0f};
    const int pb = tid >> 4;        // batch base for pointwise (s adds 16)
    const int pj = tid & 15;        // unit within group

    for (int t = 0; t < TT; t++) {
        const __nv_bfloat16* __restrict__ hin  = g_hbuf[t & 1];
        __nv_bfloat16* __restrict__       hout = g_hbuf[(t + 1) & 1];

        // xg prefetch (DRAM latency hidden behind the whole step)
        float xv[2][4];
#pragma unroll
        for (int s = 0; s < 2; s++) {
            int b = pb + s * 16;
            const float* xp = g_xg + ((size_t)(b0 + b) * TT + t) * G4 + j0 + pj;
            xv[s][0] = xp[0];
            xv[s][1] = xp[HH];
            xv[s][2] = xp[2 * HH];
            xv[s][3] = xp[3 * HH];
        }

        // wait for all producers of this batch half to publish h for step t
        if (tid < 64) {
            while ((int)ld_acq(&g_flags[bh * 64 + tid]) < t) {}
        }
        __syncthreads();

        // issue all 4 h-chunk loads (cp.async, one group per chunk)
#pragma unroll
        for (int kc = 0; kc < 4; kc++) {
#pragma unroll
            for (int r = 0; r < 4; r++) {
                int lin = tid + r * 256;
                int row = lin >> 5, c8 = (lin & 31) * 8;
                cp16(smem_u32(Asm + kc * (32 * AS2) + row * AS2 + c8),
                     hin + (size_t)(b0 + row) * HH + kc * KC + c8);
            }
            CP_COMMIT();
        }

        float acc[2][4];
#pragma unroll
        for (int ns = 0; ns < 2; ns++)
#pragma unroll
            for (int q = 0; q < 4; q++) acc[ns][q] = 0.0f;

        auto compute = [&](int kc) {
            const __nv_bfloat16* Ab = Asm + kc * (32 * AS2);
#pragma unroll
            for (int q = 0; q < 16; q++) {
                uint32_t af[4], bf4[4];
                ldsm4(af, smem_u32(Ab + (wm + lrow) * AS2 + q * 16 + lhi));
                ldsm4(bf4, smem_u32(Wsm + (wn + lrow) * WS2 + kc * KC + q * 16 + lhi));
                mma_bf16(acc[0], af, bf4[0], bf4[2]);
                mma_bf16(acc[1], af, bf4[1], bf4[3]);
            }
        };

        cp_wait<3>(); __syncthreads(); compute(0);
        cp_wait<2>(); __syncthreads(); compute(1);
        cp_wait<1>(); __syncthreads(); compute(2);
        cp_wait<0>(); __syncthreads(); compute(3);

        // gate exchange through SMEM
#pragma unroll
        for (int ns = 0; ns < 2; ns++) {
            int col = wn + ns * 8 + 2 * tq;
            int row = wm + g;
            Gsm[row * 65 + col]           = acc[ns][0];
            Gsm[row * 65 + col + 1]       = acc[ns][1];
            Gsm[(row + 8) * 65 + col]     = acc[ns][2];
            Gsm[(row + 8) * 65 + col + 1] = acc[ns][3];
        }
        __syncthreads();

        // pointwise LSTM update (2 cells per thread)
        __nv_bfloat16 hb[2];
#pragma unroll
        for (int s = 0; s < 2; s++) {
            int b = pb + s * 16;
            float iv = Gsm[b * 65 + pj]      + xv[s][0];
            float fv = Gsm[b * 65 + 16 + pj] + xv[s][1];
            float gv = Gsm[b * 65 + 32 + pj] + xv[s][2];
            float ov = Gsm[b * 65 + 48 + pj] + xv[s][3];

            float cn = sigf(fv) * cst[s] + sigf(iv) * tanhf(gv);
            float hn = sigf(ov) * tanhf(cn);
            cst[s] = cn;
            hb[s]  = __float2bfloat16(hn);
            hout[(b0 + b) * HH + j0 + pj] = hb[s];
        }
        __syncthreads();

        if (tid == 0) {
            __threadfence();
            st_rel(&g_flags[bh * 64 + ug], (unsigned)(t + 1));
        }

        // hidden-sequence store off the critical path (after flag release)
        if (hs_sel) {
            __nv_bfloat16* __restrict__ hs = (hs_sel == 1) ? g_hs_a : g_hs_b;
#pragma unroll
            for (int s = 0; s < 2; s++) {
                int b = pb + s * 16;
                hs[((size_t)(b0 + b) * TT + t) * HH + j0 + pj] = hb[s];
            }
        }
    }
}

// ---------------------------------------------------------------------------
// Reset h state + flags before each layer
// ---------------------------------------------------------------------------
__global__ void reset_kernel()
{
    int i = blockIdx.x * blockDim.x + threadIdx.x;
    if (i < BB * HH) {
        g_hbuf[0][i] = __float2bfloat16(0.0f);
        g_hbuf[1][i] = __float2bfloat16(0.0f);
    }
    if (i < NCTA) g_flags[i] = 0;
}

// ---------------------------------------------------------------------------
// Projection GEMM (all-bf16, cp.async 3-stage, ldmatrix, 128x128 tile):
// g_xg[M,4096] = A[M,K] @ W[4096,K]^T + b1 + b2,  M = B*T = 16384
// ---------------------------------------------------------------------------
__global__ void __launch_bounds__(256, 2)
proj_kernel(int a_sel, size_t w_off, const float* __restrict__ b1v,
            const float* __restrict__ b2v, int K)
{
    extern __shared__ __align__(16) unsigned char smem[];
    __nv_bfloat16* Asb = (__nv_bfloat16*)smem;    // [3][128][PS]
    __nv_bfloat16* Bsb = Asb + 3 * PTILE;         // [3][128][PS]
    float*         bsm = (float*)(Bsb + 3 * PTILE);

    const __nv_bfloat16* __restrict__ A =
        (a_sel == 0) ? g_xb : (a_sel == 1 ? g_hs_a : g_hs_b);
    const __nv_bfloat16* __restrict__ W = g_wb + w_off;

    const int tid  = threadIdx.x;
    const int m0   = blockIdx.y * 128;
    const int n0   = blockIdx.x * 128;
    const int warp = tid >> 5, lane = tid & 31;
    const int g    = lane >> 2, tq = lane & 3;
    const int wmw  = (warp >> 1) * 32;    // 0/32/64/96
    const int wnw  = (warp & 1) * 64;     // 0/64
    const int lrow = lane & 15;
    const int lhi  = (lane >> 4) * 8;

    if (tid < 128) bsm[tid] = b1v[n0 + tid] + b2v[n0 + tid];

    float acc[2][8][4];
#pragma unroll
    for (int i = 0; i < 2; i++)
#pragma unroll
        for (int j = 0; j < 8; j++)
#pragma unroll
            for (int q = 0; q < 4; q++) acc[i][j][q] = 0.0f;

    auto load = [&](int kc, int st) {
#pragma unroll
        for (int r = 0; r < 2; r++) {
            int lin = tid + r * 256;
            int row = lin >> 2, c8 = (lin & 3) * 8;
            cp16(smem_u32(Asb + st * PTILE + row * PS + c8),
                 A + (size_t)(m0 + row) * K + kc * 32 + c8);
            cp16(smem_u32(Bsb + st * PTILE + row * PS + c8),
                 W + (size_t)(n0 + row) * K + kc * 32 + c8);
        }
    };

    auto compute = [&](int st) {
        const __nv_bfloat16* Ab = Asb + st * PTILE;
        const __nv_bfloat16* Bb = Bsb + st * PTILE;
#pragma unroll
        for (int q = 0; q < 2; q++) {
            uint32_t af[2][4], bf4[4][4];
            ldsm4(af[0], smem_u32(Ab + (wmw + lrow) * PS + q * 16 + lhi));
            ldsm4(af[1], smem_u32(Ab + (wmw + 16 + lrow) * PS + q * 16 + lhi));
#pragma unroll
            for (int jn = 0; jn < 4; jn++)
                ldsm4(bf4[jn], smem_u32(Bb + (wnw + jn * 16 + lrow) * PS + q * 16 + lhi));
#pragma unroll
            for (int i = 0; i < 2; i++)
#pragma unroll
                for (int j8 = 0; j8 < 8; j8++)
                    mma_bf16(acc[i][j8], af[i],
                             bf4[j8 >> 1][j8 & 1], bf4[j8 >> 1][(j8 & 1) + 2]);
        }
    };

    const int nk = K / 32;
    load(0, 0); CP_COMMIT();
    load(1, 1); CP_COMMIT();
#pragma unroll 1
    for (int kc = 0; kc < nk; kc++) {
        cp_wait<1>();
        __syncthreads();
        if (kc + 2 < nk) load(kc + 2, (kc + 2) % 3);
        CP_COMMIT();
        compute(kc % 3);
    }

    // epilogue: add biases, store fp32 to g_xg
#pragma unroll
    for (int i = 0; i < 2; i++)
#pragma unroll
        for (int j8 = 0; j8 < 8; j8++) {
            int row  = m0 + wmw + i * 16 + g;
            int lcol = wnw + j8 * 8 + 2 * tq;
            int col  = n0 + lcol;
            float bb0 = bsm[lcol], bb1 = bsm[lcol + 1];
            g_xg[(size_t)row * G4 + col]           = acc[i][j8][0] + bb0;
            g_xg[(size_t)row * G4 + col + 1]       = acc[i][j8][1] + bb1;
            g_xg[(size_t)(row + 8) * G4 + col]     = acc[i][j8][2] + bb0;
            g_xg[(size_t)(row + 8) * G4 + col + 1] = acc[i][j8][3] + bb1;
        }
}

// ---------------------------------------------------------------------------
// Final FC: out[b] = dot(h_final[b,:], fc_w) + fc_b[0];  h_final = g_hbuf[0]
// ---------------------------------------------------------------------------
__global__ void fc_kernel(const float* __restrict__ fw,
                          const float* __restrict__ fb,
                          float* __restrict__ out)
{
    __shared__ float red[8];
    int b   = blockIdx.x;
    int tid = threadIdx.x;
    const __nv_bfloat16* __restrict__ hr = g_hbuf[0] + b * HH;

    float s = 0.0f;
    for (int j = tid; j < HH; j += blockDim.x)
        s += __bfloat162float(hr[j]) * fw[j];

#pragma unroll
    for (int o = 16; o > 0; o >>= 1) s += __shfl_down_sync(0xffffffffu, s, o);
    if ((tid & 31) == 0) red[tid >> 5] = s;
    __syncthreads();
    if (tid == 0) {
        float tot = 0.0f;
        for (int w = 0; w < 8; w++) tot += red[w];
        out[b] = tot + fb[0];
    }
}

// ---------------------------------------------------------------------------
// Launch sequence (graph-capturable, kernels only)
// ---------------------------------------------------------------------------
extern "C" void kernel_launch(void* const* d_in, const int* in_sizes, int n_in,
                              void* d_out, int out_size)
{
    const float* x       = (const float*)d_in[0];
    const float* w_ih[3] = { (const float*)d_in[1], (const float*)d_in[5], (const float*)d_in[9]  };
    const float* w_hh[3] = { (const float*)d_in[2], (const float*)d_in[6], (const float*)d_in[10] };
    const float* b_ih[3] = { (const float*)d_in[3], (const float*)d_in[7], (const float*)d_in[11] };
    const float* b_hh[3] = { (const float*)d_in[4], (const float*)d_in[8], (const float*)d_in[12] };
    const float* fc_w    = (const float*)d_in[13];
    const float* fc_b    = (const float*)d_in[14];
    float* out = (float*)d_out;

    cudaFuncSetAttribute(persist_kernel,
                         cudaFuncAttributeMaxDynamicSharedMemorySize, PERSIST_SMEM);
    cudaFuncSetAttribute(proj_kernel,
                         cudaFuncAttributeMaxDynamicSharedMemorySize, PROJ_SMEM);

    // one-time bf16 conversions: x, w_ih0/1/2
    conv_kernel<<<(1048576 + 255) / 256, 256>>>(x,       0, 0,       1048576);
    conv_kernel<<<(262144  + 255) / 256, 256>>>(w_ih[0], 1, 0,       262144);
    conv_kernel<<<(1048576 + 255) / 256, 256>>>(w_ih[1], 1, 1048576, 1048576);
    conv_kernel<<<(1048576 + 255) / 256, 256>>>(w_ih[2], 1, 5242880, 1048576);

    const int    a_sel[3]  = { 0, 1, 2 };
    const int    hs_sel[3] = { 1, 2, 0 };
    const int    K_in[3]   = { DIN, HH, HH };
    const size_t w_off[3]  = { 0, 1048576, 5242880 };

    dim3 pgrid(32, 128);

    for (int l = 0; l < 3; l++) {
        proj_kernel<<<pgrid, 256, PROJ_SMEM>>>(a_sel[l], w_off[l], b_ih[l], b_hh[l], K_in[l]);
        reset_kernel<<<(BB * HH + 255) / 256, 256>>>();
        persist_kernel<<<NCTA, 256, PERSIST_SMEM>>>(w_hh[l], hs_sel[l]);
    }
    fc_kernel<<<BB, 256>>>(fc_w, fc_b, out);
}

// round 8
// speedup vs baseline: 5.5995x; 1.6714x over previous
#include <cuda_runtime.h>
#include <cuda_bf16.h>
#include <cstdint>
#include <cstddef>

// Problem constants
#define BB   64
#define TT   256
#define DIN  256
#define HH   1024
#define G4   4096
#define NCTA 128

// persist smem layout (bf16 elems)
#define WS2  1032            // weight row stride (1024 + 8)
#define AS2  264             // h chunk row stride (256 + 8)
#define KC   256             // K chunk
#define PERSIST_SMEM 208128  // 64*1032*2 + 4*32*264*2 + 32*66*4

// proj smem layout
#define PS    40             // row stride elems (32 + 8)
#define PTILE (128*PS)       // elems per stage per operand
#define PROJ_SMEM (3*PTILE*2*2 + 512)

// flag padding: 64 u32 = 256B per flag -> distinct L2 slices
#define FPAD 64

// ---------------------------------------------------------------------------
// Scratch (allocation-free: __device__ globals)
// ---------------------------------------------------------------------------
__device__ __align__(128) float          g_xg[(size_t)BB * TT * G4];
__device__ __align__(128) __nv_bfloat16  g_hs_a[(size_t)BB * TT * HH];
__device__ __align__(128) __nv_bfloat16  g_hs_b[(size_t)BB * TT * HH];
__device__ __align__(128) __nv_bfloat16  g_hbuf[2][BB * HH];
__device__ __align__(128) __nv_bfloat16  g_xb[(size_t)BB * TT * DIN];
__device__ __align__(128) __nv_bfloat16  g_wb[(size_t)(G4 * DIN + 2 * G4 * HH)];
__device__ __align__(128) unsigned       g_flags[NCTA * FPAD];

// ---------------------------------------------------------------------------
// helpers
// ---------------------------------------------------------------------------
__device__ __forceinline__ uint32_t packbf(float lo, float hi) {
    uint32_t r;
    asm("cvt.rn.bf16x2.f32 %0, %1, %2;" : "=r"(r) : "f"(hi), "f"(lo));
    return r;
}

__device__ __forceinline__ void mma_bf16(float c[4], const uint32_t a[4],
                                         uint32_t b0, uint32_t b1) {
    asm volatile(
        "mma.sync.aligned.m16n8k16.row.col.f32.bf16.bf16.f32 "
        "{%0,%1,%2,%3}, {%4,%5,%6,%7}, {%8,%9}, {%0,%1,%2,%3};\n"
        : "+f"(c[0]), "+f"(c[1]), "+f"(c[2]), "+f"(c[3])
        : "r"(a[0]), "r"(a[1]), "r"(a[2]), "r"(a[3]), "r"(b0), "r"(b1));
}

__device__ __forceinline__ uint32_t smem_u32(const void* p) {
    return (uint32_t)__cvta_generic_to_shared(p);
}

__device__ __forceinline__ void ldsm4(uint32_t r[4], uint32_t addr) {
    asm volatile("ldmatrix.sync.aligned.m8n8.x4.shared.b16 {%0,%1,%2,%3}, [%4];\n"
                 : "=r"(r[0]), "=r"(r[1]), "=r"(r[2]), "=r"(r[3]) : "r"(addr));
}

__device__ __forceinline__ void cp16(uint32_t daddr, const void* src) {
    asm volatile("cp.async.cg.shared.global [%0], [%1], 16;\n"
                 :: "r"(daddr), "l"(src));
}
#define CP_COMMIT() asm volatile("cp.async.commit_group;\n")
template <int N> __device__ __forceinline__ void cp_wait() {
    asm volatile("cp.async.wait_group %0;\n" :: "n"(N));
}

__device__ __forceinline__ unsigned ld_acq(const unsigned* p) {
    unsigned v;
    asm volatile("ld.acquire.gpu.u32 %0, [%1];" : "=r"(v) : "l"(p));
    return v;
}
__device__ __forceinline__ void st_rel(unsigned* p, unsigned v) {
    asm volatile("st.release.gpu.u32 [%0], %1;" :: "l"(p), "r"(v));
}

__device__ __forceinline__ float sigf(float x) { return 1.0f / (1.0f + __expf(-x)); }

// ---------------------------------------------------------------------------
// Convert stage A: x -> bf16
// ---------------------------------------------------------------------------
__global__ void convA_kernel(const float* __restrict__ x)
{
    int i = blockIdx.x * blockDim.x + threadIdx.x;
    if (i >= (BB * TT * DIN) / 4) return;
    float4 v = ((const float4*)x)[i];
    uint32_t* d = (uint32_t*)g_xb + (size_t)i * 2;
    d[0] = packbf(v.x, v.y);
    d[1] = packbf(v.z, v.w);
}

// ---------------------------------------------------------------------------
// Convert stage B: w_ih0/1/2 -> bf16, and zero the sync flags (per launch)
// ---------------------------------------------------------------------------
__global__ void convB_kernel(const float* __restrict__ w0,
                             const float* __restrict__ w1,
                             const float* __restrict__ w2)
{
    int i = blockIdx.x * blockDim.x + threadIdx.x;
    if (i < NCTA * FPAD) g_flags[i] = 0;
    if (i < (G4 * DIN) / 4) {
        float4 v = ((const float4*)w0)[i];
        uint32_t* d = (uint32_t*)g_wb + (size_t)i * 2;
        d[0] = packbf(v.x, v.y);
        d[1] = packbf(v.z, v.w);
    }
    if (i < (G4 * HH) / 4) {
        float4 v = ((const float4*)w1)[i];
        uint32_t* d = (uint32_t*)(g_wb + (size_t)G4 * DIN) + (size_t)i * 2;
        d[0] = packbf(v.x, v.y);
        d[1] = packbf(v.z, v.w);
        float4 u = ((const float4*)w2)[i];
        uint32_t* e = (uint32_t*)(g_wb + (size_t)G4 * (DIN + HH)) + (size_t)i * 2;
        e[0] = packbf(u.x, u.y);
        e[1] = packbf(u.z, u.w);
    }
}

// ---------------------------------------------------------------------------
// Persistent recurrent kernel: 128 CTAs = 2 batch-halves x 64 unit-groups.
// CTA (bh, ug): batches bh*32..+31, hidden units ug*16..+15 (64 gate cols).
// Weights [64][1024] bf16 stationary in SMEM. h chunks via cp.async.
// ldmatrix + mma.m16n8k16. Monotonic padded flags (256B apart, one L2 slice
// each). t=0 skips wait/load/GEMM (h0 == 0).
// ---------------------------------------------------------------------------
__global__ void __launch_bounds__(256, 1)
persist_kernel(const float* __restrict__ Whh, int hs_sel, unsigned base)
{
    extern __shared__ __align__(16) unsigned char smem[];
    __nv_bfloat16* Wsm = (__nv_bfloat16*)smem;            // [64][WS2]
    __nv_bfloat16* Asm = Wsm + 64 * WS2;                  // [4][32][AS2]
    float*         Gsm = (float*)(Asm + 4 * 32 * AS2);    // [32][66]

    const int tid  = threadIdx.x;
    const int cta  = blockIdx.x;
    const int bh   = cta >> 6;
    const int ug   = cta & 63;
    const int j0   = ug * 16;
    const int b0   = bh * 32;
    const int warp = tid >> 5, lane = tid & 31;
    const int g    = lane >> 2, tq = lane & 3;
    const int wm   = (warp >> 2) * 16;    // 0 / 16
    const int wn   = (warp & 3) * 16;     // 0 / 16 / 32 / 48
    const int lrow = lane & 15;
    const int lhi  = (lane >> 4) * 8;

    // pointwise mapping: 2 adjacent units per thread
    const int pb = tid >> 3;              // batch 0..31
    const int pu = (tid & 7) * 2;         // unit pair 0,2,..,14

    // my poll address (one flag per polling thread)
    const unsigned* poll_p = &g_flags[(bh * 64 + (tid & 63)) * FPAD];
    unsigned* my_flag = &g_flags[(bh * 64 + ug) * FPAD];

    // ---- gather + convert weights (once per layer) ----
    for (int idx = tid; idx < 64 * 256; idx += 256) {
        int n = idx >> 8;  int k4 = (idx & 255) * 4;
        int gate = n >> 4, u = n & 15;
        float4 w = *(const float4*)(Whh + (size_t)(gate * HH + j0 + u) * HH + k4);
        uint32_t* dst = (uint32_t*)(Wsm + n * WS2 + k4);
        dst[0] = packbf(w.x, w.y);
        dst[1] = packbf(w.z, w.w);
    }
    __syncthreads();

    float cst[2] = {0.0f, 0.0f};

    for (int t = 0; t < TT; t++) {
        const __nv_bfloat16* __restrict__ hin  = g_hbuf[t & 1];
        __nv_bfloat16* __restrict__       hout = g_hbuf[(t + 1) & 1];

        // xg prefetch (float2 per gate; DRAM latency hidden behind wait/GEMM)
        float2 xv[4];
        {
            const float* xp = g_xg + ((size_t)(b0 + pb) * TT + t) * G4 + j0 + pu;
            xv[0] = *(const float2*)(xp);
            xv[1] = *(const float2*)(xp + HH);
            xv[2] = *(const float2*)(xp + 2 * HH);
            xv[3] = *(const float2*)(xp + 3 * HH);
        }

        float acc[2][4];
#pragma unroll
        for (int ns = 0; ns < 2; ns++)
#pragma unroll
            for (int q = 0; q < 4; q++) acc[ns][q] = 0.0f;

        if (t > 0) {
            // wait for all producers of this batch half (padded flags)
            if (tid < 64) {
                while ((int)ld_acq(poll_p) < (int)(base + t)) {}
            }
            __syncthreads();

            // issue all 4 h-chunk loads (cp.async, one group per chunk)
#pragma unroll
            for (int kc = 0; kc < 4; kc++) {
#pragma unroll
                for (int r = 0; r < 4; r++) {
                    int lin = tid + r * 256;
                    int row = lin >> 5, c8 = (lin & 31) * 8;
                    cp16(smem_u32(Asm + kc * (32 * AS2) + row * AS2 + c8),
                         hin + (size_t)(b0 + row) * HH + kc * KC + c8);
                }
                CP_COMMIT();
            }

            auto compute = [&](int kc) {
                const __nv_bfloat16* Ab = Asm + kc * (32 * AS2);
#pragma unroll
                for (int q = 0; q < 16; q++) {
                    uint32_t af[4], bf4[4];
                    ldsm4(af, smem_u32(Ab + (wm + lrow) * AS2 + q * 16 + lhi));
                    ldsm4(bf4, smem_u32(Wsm + (wn + lrow) * WS2 + kc * KC + q * 16 + lhi));
                    mma_bf16(acc[0], af, bf4[0], bf4[2]);
                    mma_bf16(acc[1], af, bf4[1], bf4[3]);
                }
            };

            cp_wait<3>(); __syncthreads(); compute(0);
            cp_wait<2>(); __syncthreads(); compute(1);
            cp_wait<1>(); __syncthreads(); compute(2);
            cp_wait<0>(); __syncthreads(); compute(3);
        }

        // gate exchange through SMEM
#pragma unroll
        for (int ns = 0; ns < 2; ns++) {
            int col = wn + ns * 8 + 2 * tq;
            int row = wm + g;
            Gsm[row * 66 + col]           = acc[ns][0];
            Gsm[row * 66 + col + 1]       = acc[ns][1];
            Gsm[(row + 8) * 66 + col]     = acc[ns][2];
            Gsm[(row + 8) * 66 + col + 1] = acc[ns][3];
        }
        __syncthreads();

        // pointwise LSTM update: 2 adjacent units (pb, j0+pu / j0+pu+1)
        uint32_t hpack;
        {
            float i0 = Gsm[pb * 66 + pu]          + xv[0].x;
            float i1 = Gsm[pb * 66 + pu + 1]      + xv[0].y;
            float f0 = Gsm[pb * 66 + 16 + pu]     + xv[1].x;
            float f1 = Gsm[pb * 66 + 16 + pu + 1] + xv[1].y;
            float g0 = Gsm[pb * 66 + 32 + pu]     + xv[2].x;
            float g1 = Gsm[pb * 66 + 32 + pu + 1] + xv[2].y;
            float o0 = Gsm[pb * 66 + 48 + pu]     + xv[3].x;
            float o1 = Gsm[pb * 66 + 48 + pu + 1] + xv[3].y;

            float c0 = sigf(f0) * cst[0] + sigf(i0) * tanhf(g0);
            float c1 = sigf(f1) * cst[1] + sigf(i1) * tanhf(g1);
            float h0 = sigf(o0) * tanhf(c0);
            float h1 = sigf(o1) * tanhf(c1);
            cst[0] = c0; cst[1] = c1;

            hpack = packbf(h0, h1);
            *(uint32_t*)(hout + (size_t)(b0 + pb) * HH + j0 + pu) = hpack;
        }
        __syncthreads();

        if (tid == 0) {
            __threadfence();
            st_rel(my_flag, base + (unsigned)t + 1);
        }

        // hidden-sequence store off the critical path (after flag release)
        if (hs_sel) {
            __nv_bfloat16* __restrict__ hs = (hs_sel == 1) ? g_hs_a : g_hs_b;
            *(uint32_t*)(hs + ((size_t)(b0 + pb) * TT + t) * HH + j0 + pu) = hpack;
        }
    }
}

// ---------------------------------------------------------------------------
// Projection GEMM (all-bf16, cp.async 3-stage, ldmatrix, 128x128 tile):
// g_xg[M,4096] = A[M,K] @ W[4096,K]^T + b1 + b2,  M = B*T = 16384
// ---------------------------------------------------------------------------
__global__ void __launch_bounds__(256, 2)
proj_kernel(int a_sel, size_t w_off, const float* __restrict__ b1v,
            const float* __restrict__ b2v, int K)
{
    extern __shared__ __align__(16) unsigned char smem[];
    __nv_bfloat16* Asb = (__nv_bfloat16*)smem;    // [3][128][PS]
    __nv_bfloat16* Bsb = Asb + 3 * PTILE;         // [3][128][PS]
    float*         bsm = (float*)(Bsb + 3 * PTILE);

    const __nv_bfloat16* __restrict__ A =
        (a_sel == 0) ? g_xb : (a_sel == 1 ? g_hs_a : g_hs_b);
    const __nv_bfloat16* __restrict__ W = g_wb + w_off;

    const int tid  = threadIdx.x;
    const int m0   = blockIdx.y * 128;
    const int n0   = blockIdx.x * 128;
    const int warp = tid >> 5, lane = tid & 31;
    const int g    = lane >> 2, tq = lane & 3;
    const int wmw  = (warp >> 1) * 32;    // 0/32/64/96
    const int wnw  = (warp & 1) * 64;     // 0/64
    const int lrow = lane & 15;
    const int lhi  = (lane >> 4) * 8;

    if (tid < 128) bsm[tid] = b1v[n0 + tid] + b2v[n0 + tid];

    float acc[2][8][4];
#pragma unroll
    for (int i = 0; i < 2; i++)
#pragma unroll
        for (int j = 0; j < 8; j++)
#pragma unroll
            for (int q = 0; q < 4; q++) acc[i][j][q] = 0.0f;

    auto load = [&](int kc, int st) {
#pragma unroll
        for (int r = 0; r < 2; r++) {
            int lin = tid + r * 256;
            int row = lin >> 2, c8 = (lin & 3) * 8;
            cp16(smem_u32(Asb + st * PTILE + row * PS + c8),
                 A + (size_t)(m0 + row) * K + kc * 32 + c8);
            cp16(smem_u32(Bsb + st * PTILE + row * PS + c8),
                 W + (size_t)(n0 + row) * K + kc * 32 + c8);
        }
    };

    auto compute = [&](int st) {
        const __nv_bfloat16* Ab = Asb + st * PTILE;
        const __nv_bfloat16* Bb = Bsb + st * PTILE;
#pragma unroll
        for (int q = 0; q < 2; q++) {
            uint32_t af[2][4], bf4[4][4];
            ldsm4(af[0], smem_u32(Ab + (wmw + lrow) * PS + q * 16 + lhi));
            ldsm4(af[1], smem_u32(Ab + (wmw + 16 + lrow) * PS + q * 16 + lhi));
#pragma unroll
            for (int jn = 0; jn < 4; jn++)
                ldsm4(bf4[jn], smem_u32(Bb + (wnw + jn * 16 + lrow) * PS + q * 16 + lhi));
#pragma unroll
            for (int i = 0; i < 2; i++)
#pragma unroll
                for (int j8 = 0; j8 < 8; j8++)
                    mma_bf16(acc[i][j8], af[i],
                             bf4[j8 >> 1][j8 & 1], bf4[j8 >> 1][(j8 & 1) + 2]);
        }
    };

    const int nk = K / 32;
    load(0, 0); CP_COMMIT();
    load(1, 1); CP_COMMIT();
#pragma unroll 1
    for (int kc = 0; kc < nk; kc++) {
        cp_wait<1>();
        __syncthreads();
        if (kc + 2 < nk) load(kc + 2, (kc + 2) % 3);
        CP_COMMIT();
        compute(kc % 3);
    }

    // epilogue: add biases, store fp32 to g_xg
#pragma unroll
    for (int i = 0; i < 2; i++)
#pragma unroll
        for (int j8 = 0; j8 < 8; j8++) {
            int row  = m0 + wmw + i * 16 + g;
            int lcol = wnw + j8 * 8 + 2 * tq;
            int col  = n0 + lcol;
            float bb0 = bsm[lcol], bb1 = bsm[lcol + 1];
            g_xg[(size_t)row * G4 + col]           = acc[i][j8][0] + bb0;
            g_xg[(size_t)row * G4 + col + 1]       = acc[i][j8][1] + bb1;
            g_xg[(size_t)(row + 8) * G4 + col]     = acc[i][j8][2] + bb0;
            g_xg[(size_t)(row + 8) * G4 + col + 1] = acc[i][j8][3] + bb1;
        }
}

// ---------------------------------------------------------------------------
// Final FC: out[b] = dot(h_final[b,:], fc_w) + fc_b[0];  h_final = g_hbuf[0]
// ---------------------------------------------------------------------------
__global__ void fc_kernel(const float* __restrict__ fw,
                          const float* __restrict__ fb,
                          float* __restrict__ out)
{
    __shared__ float red[8];
    int b   = blockIdx.x;
    int tid = threadIdx.x;
    const __nv_bfloat16* __restrict__ hr = g_hbuf[0] + b * HH;

    float s = 0.0f;
    for (int j = tid; j < HH; j += blockDim.x)
        s += __bfloat162float(hr[j]) * fw[j];

#pragma unroll
    for (int o = 16; o > 0; o >>= 1) s += __shfl_down_sync(0xffffffffu, s, o);
    if ((tid & 31) == 0) red[tid >> 5] = s;
    __syncthreads();
    if (tid == 0) {
        float tot = 0.0f;
        for (int w = 0; w < 8; w++) tot += red[w];
        out[b] = tot + fb[0];
    }
}

// ---------------------------------------------------------------------------
// Launch sequence (graph-capturable, kernels only):
// convA, convB, (proj, persist) x3, fc  -> persist1 is launch #6 for ncu
// ---------------------------------------------------------------------------
extern "C" void kernel_launch(void* const* d_in, const int* in_sizes, int n_in,
                              void* d_out, int out_size)
{
    const float* x       = (const float*)d_in[0];
    const float* w_ih[3] = { (const float*)d_in[1], (const float*)d_in[5], (const float*)d_in[9]  };
    const float* w_hh[3] = { (const float*)d_in[2], (const float*)d_in[6], (const float*)d_in[10] };
    const float* b_ih[3] = { (const float*)d_in[3], (const float*)d_in[7], (const float*)d_in[11] };
    const float* b_hh[3] = { (const float*)d_in[4], (const float*)d_in[8], (const float*)d_in[12] };
    const float* fc_w    = (const float*)d_in[13];
    const float* fc_b    = (const float*)d_in[14];
    float* out = (float*)d_out;

    cudaFuncSetAttribute(persist_kernel,
                         cudaFuncAttributeMaxDynamicSharedMemorySize, PERSIST_SMEM);
    cudaFuncSetAttribute(proj_kernel,
                         cudaFuncAttributeMaxDynamicSharedMemorySize, PROJ_SMEM);

    convA_kernel<<<(BB * TT * DIN / 4 + 255) / 256, 256>>>(x);
    convB_kernel<<<(G4 * HH / 4 + 255) / 256, 256>>>(w_ih[0], w_ih[1], w_ih[2]);

    const int    a_sel[3]  = { 0, 1, 2 };
    const int    hs_sel[3] = { 1, 2, 0 };
    const int    K_in[3]   = { DIN, HH, HH };
    const size_t w_off[3]  = { 0, (size_t)G4 * DIN, (size_t)G4 * (DIN + HH) };

    dim3 pgrid(32, 128);

    for (int l = 0; l < 3; l++) {
        proj_kernel<<<pgrid, 256, PROJ_SMEM>>>(a_sel[l], w_off[l], b_ih[l], b_hh[l], K_in[l]);
        persist_kernel<<<NCTA, 256, PERSIST_SMEM>>>(w_hh[l], hs_sel[l],
                                                    (unsigned)(l * TT));
    }
    fc_kernel<<<BB, 256>>>(fc_w, fc_b, out);
}